// round 17
// baseline (speedup 1.0000x reference)
#include <cuda_runtime.h>
#include <cstdint>

// E[b] = sum over strict-lower-tri pairs (i,j): flat[b,p] * rsqrt(r^2(i,j)).
// Row-group compute (G1..G4 by j-step count) + CHUNKED TMA pipeline:
// 3 TMA chunks matching G1/G2/G3 flat ranges, one mbarrier each, so copy
// streams while earlier groups compute (fixes the burst/idle DRAM pattern).
// G4 + misaligned stragglers staged via LDG in the prologue.

#define BATCH   2048
#define NATOMS  100
#define NC2     4950
#define TPB     256
#define NWARPS  (TPB / 32)
#define BPB     2

#define C1E 528            // G1 rows 1..32   -> flat [0,528)
#define C2E 2080           // G2 rows 33..64  -> [528,2080)
#define C3E 4656           // G3 rows 65..96  -> [2080,4656)
#define SROW1 4954         // smem offset of batch-1 row (keeps 16B dst align)
#define SFLAT_LEN 9952

__device__ __forceinline__ uint32_t smem_u32(const void* p) {
    uint32_t a;
    asm("{ .reg .u64 t; cvta.to.shared.u64 t, %1; cvt.u32.u64 %0, t; }"
        : "=r"(a) : "l"(p));
    return a;
}

__device__ __forceinline__ void tma_1d(uint32_t dst, const float* src,
                                       unsigned bytes, uint32_t mb) {
    asm volatile("cp.async.bulk.shared::cta.global.mbarrier::complete_tx::bytes"
                 " [%0], [%1], %2, [%3];"
                 :: "r"(dst), "l"(src), "r"(bytes), "r"(mb) : "memory");
}

__device__ __forceinline__ void mbar_wait(uint32_t mb) {
    uint32_t done;
    do {
        asm volatile("{ .reg .pred p;"
                     "  mbarrier.try_wait.parity.shared.b64 p, [%1], 0, 0x989680;"
                     "  selp.b32 %0, 1, 0, p; }"
                     : "=r"(done) : "r"(mb) : "memory");
    } while (!done);
}

template<int NFULL>
__device__ __forceinline__ void rows_group(
    int lo, int hi, int wid, int lane,
    const float4* __restrict__ scB4, const float* __restrict__ sflat,
    float& acc0, float& acc1)
{
    float4 cj0[NFULL + 1], cj1[NFULL + 1];
    #pragma unroll
    for (int jb = 0; jb <= NFULL; ++jb) {
        const int j = jb * 32 + lane;
        cj0[jb] = scB4[j * 2 + 0];
        cj1[jb] = scB4[j * 2 + 1];
    }

    for (int i = lo + wid; i <= hi; i += NWARPS) {
        const float4 ci0 = scB4[i * 2 + 0];
        const float4 ci1 = scB4[i * 2 + 1];
        int off = i * (i - 1) / 2 + lane;

        #pragma unroll
        for (int jb = 0; jb < NFULL; ++jb, off += 32) {
            const float v0 = sflat[off];
            const float v1 = sflat[off + SROW1];

            const float d0 = fmaf(ci0.x, cj0[jb].x,
                             fmaf(ci0.y, cj0[jb].y, ci0.z * cj0[jb].z));
            const float r0 = fmaf(-2.f, d0, ci0.w + cj0[jb].w);
            const float d1 = fmaf(ci1.x, cj1[jb].x,
                             fmaf(ci1.y, cj1[jb].y, ci1.z * cj1[jb].z));
            const float r1 = fmaf(-2.f, d1, ci1.w + cj1[jb].w);

            acc0 = fmaf(v0, rsqrtf(r0), acc0);
            acc1 = fmaf(v1, rsqrtf(r1), acc1);
        }

        { // masked diagonal step
            const bool valid = lane < (i - NFULL * 32);
            const float v0 = sflat[off];
            const float v1 = sflat[off + SROW1];

            const float d0 = fmaf(ci0.x, cj0[NFULL].x,
                             fmaf(ci0.y, cj0[NFULL].y, ci0.z * cj0[NFULL].z));
            const float r0 = fmaf(-2.f, d0, ci0.w + cj0[NFULL].w);
            const float d1 = fmaf(ci1.x, cj1[NFULL].x,
                             fmaf(ci1.y, cj1[NFULL].y, ci1.z * cj1[NFULL].z));
            const float r1 = fmaf(-2.f, d1, ci1.w + cj1[NFULL].w);

            const float q0 = rsqrtf(r0);
            const float q1 = rsqrtf(r1);
            if (valid) acc0 = fmaf(v0, q0, acc0);
            if (valid) acc1 = fmaf(v1, q1, acc1);
        }
    }
}

__global__ __launch_bounds__(TPB, 5)
void eij_kernel(const float* __restrict__ coords,
                const float* __restrict__ flat,
                float* __restrict__ out)
{
    __shared__ __align__(16) float  sflat[SFLAT_LEN];   // ~38.9 KB
    __shared__ float4 scB4[128 * BPB];                  // (x,y,z,n), padded
    __shared__ float  wred[BPB][NWARPS];
    __shared__ __align__(8) unsigned long long mbar[3];

    const int b0   = blockIdx.x * BPB;
    const int t    = threadIdx.x;
    const int lane = t & 31;
    const int wid  = t >> 5;

    const uint32_t mb0 = smem_u32(&mbar[0]);
    const uint32_t mb1 = smem_u32(&mbar[1]);
    const uint32_t mb2 = smem_u32(&mbar[2]);

    if (t == 0) {
        asm volatile("mbarrier.init.shared.b64 [%0], 1;" :: "r"(mb0) : "memory");
        asm volatile("mbarrier.init.shared.b64 [%0], 1;" :: "r"(mb1) : "memory");
        asm volatile("mbarrier.init.shared.b64 [%0], 1;" :: "r"(mb2) : "memory");
    }
    __syncthreads();

    const float* src0 = flat + (size_t)b0 * NC2;          // 16B aligned
    const float* src1 = flat + (size_t)(b0 + 1) * NC2;    // +8B misaligned

    if (t == 0) {
        const uint32_t dst = smem_u32(sflat);
        // chunk 1: G1 range
        asm volatile("mbarrier.arrive.expect_tx.shared.b64 _, [%0], %1;"
                     :: "r"(mb0), "r"(2u * C1E * 4u) : "memory");
        tma_1d(dst,                         src0,        C1E * 4, mb0);
        tma_1d(dst + (SROW1 + 2) * 4,       src1 + 2,    C1E * 4, mb0);
        // chunk 2: G2 range
        asm volatile("mbarrier.arrive.expect_tx.shared.b64 _, [%0], %1;"
                     :: "r"(mb1), "r"(2u * (C2E - C1E) * 4u) : "memory");
        tma_1d(dst + C1E * 4,               src0 + C1E,  (C2E - C1E) * 4, mb1);
        tma_1d(dst + (SROW1 + C1E + 2) * 4, src1 + C1E + 2, (C2E - C1E) * 4, mb1);
        // chunk 3: G3 range
        asm volatile("mbarrier.arrive.expect_tx.shared.b64 _, [%0], %1;"
                     :: "r"(mb2), "r"(2u * (C3E - C2E) * 4u) : "memory");
        tma_1d(dst + C2E * 4,               src0 + C2E,  (C3E - C2E) * 4, mb2);
        tma_1d(dst + (SROW1 + C2E + 2) * 4, src1 + C2E + 2, (C3E - C2E) * 4, mb2);
    }

    // LDG-stage G4 ([4656,4950) both rows) + batch-1 stragglers e=0,1
    for (int k = t; k < (NC2 - C3E) + (NC2 - C3E - 2) + 2; k += TPB) {
        int sidx; float v;
        if (k < NC2 - C3E)                    { sidx = C3E + k;          v = src0[C3E + k]; }
        else if (k < 2 * (NC2 - C3E) - 2)     { const int e = C3E + 2 + (k - (NC2 - C3E));
                                                sidx = SROW1 + e;        v = src1[e]; }
        else                                  { const int e = k - (2 * (NC2 - C3E) - 2);
                                                sidx = SROW1 + e;        v = src1[e]; }
        sflat[sidx] = v;
    }

    // stage coords (x,y,z,n), atoms >= NATOMS zero-padded
    for (int k = t; k < 128 * BPB; k += TPB) {
        const int atom = k >> 1;
        const int q    = k & 1;
        float x = 0.f, y = 0.f, z = 0.f;
        if (atom < NATOMS) {
            const float* cp = coords + (size_t)(b0 + q) * (NATOMS * 3) + atom * 3;
            x = cp[0]; y = cp[1]; z = cp[2];
        }
        scB4[atom * 2 + q] = make_float4(x, y, z, fmaf(x, x, fmaf(y, y, z * z)));
    }
    __syncthreads();   // covers coord STS + G4 STS ordering

    float acc0 = 0.0f, acc1 = 0.0f;

    mbar_wait(mb0);
    rows_group<0>( 1, 32, wid, lane, scB4, sflat, acc0, acc1);
    mbar_wait(mb1);
    rows_group<1>(33, 64, wid, lane, scB4, sflat, acc0, acc1);
    mbar_wait(mb2);
    rows_group<2>(65, 96, wid, lane, scB4, sflat, acc0, acc1);
    rows_group<3>(97, 99, wid, lane, scB4, sflat, acc0, acc1);

    // reductions
    #pragma unroll
    for (int off = 16; off > 0; off >>= 1) {
        acc0 += __shfl_down_sync(0xFFFFFFFFu, acc0, off);
        acc1 += __shfl_down_sync(0xFFFFFFFFu, acc1, off);
    }
    if (lane == 0) { wred[0][wid] = acc0; wred[1][wid] = acc1; }
    __syncthreads();

    if (wid == 0 && lane < NWARPS) {
        float s0 = wred[0][lane];
        float s1 = wred[1][lane];
        #pragma unroll
        for (int off = NWARPS / 2; off > 0; off >>= 1) {
            s0 += __shfl_down_sync(0xFFu, s0, off);
            s1 += __shfl_down_sync(0xFFu, s1, off);
        }
        if (lane == 0) { out[b0] = s0; out[b0 + 1] = s1; }
    }
}

extern "C" void kernel_launch(void* const* d_in, const int* in_sizes, int n_in,
                              void* d_out, int out_size)
{
    const float* coords = (const float*)d_in[0];   // [2048, 100, 3]
    const float* flat   = (const float*)d_in[1];   // [2048, 4950]
    float* out          = (float*)d_out;           // [2048, 1]

    eij_kernel<<<BATCH / BPB, TPB>>>(coords, flat, out);
}